// round 7
// baseline (speedup 1.0000x reference)
#include <cuda_runtime.h>
#include <math_constants.h>

// Problem constants
#define BQ    2
#define NQ    8192
#define KNN   16
#define QPW   4                        // queries per warp
#define WPB   8                        // warps per block
#define BLOCK 256
#define QPB   (QPW * WPB)              // 32 queries per block
#define TILE  2048                     // candidates per smem tile (32 KB of float4)
#define BLOCKS_PER_BATCH (NQ / QPB)    // 256
#define NBLK  (BQ * BLOCKS_PER_BATCH)  // 512
#define FULL  0xffffffffu
#define TOTAL_EDGES ((double)(BQ) * (double)(NQ) * (double)(KNN))

// Deterministic per-block partial sums (no atomics -> same result every replay)
__device__ float g_partials[NBLK];

__global__ __launch_bounds__(BLOCK, 2)
void knn_loss_kernel(const float* __restrict__ points_ref,
                     const float* __restrict__ points)
{
    __shared__ float4 tile[TILE];      // (x, y, z, x^2+y^2+z^2)
    __shared__ float  wsum[WPB];

    const int tid  = threadIdx.x;
    const int wid  = tid >> 5;
    const int lane = tid & 31;
    const int b    = blockIdx.x / BLOCKS_PER_BATCH;
    const int q0   = (blockIdx.x % BLOCKS_PER_BATCH) * QPB + wid * QPW; // first of 4 queries

    const float* __restrict__ pr = points_ref + (size_t)b * NQ * 3;
    const float* __restrict__ pp = points     + (size_t)b * NQ * 3;

    // Query points (ref cloud) + squared norms (same expansion as reference).
    // All lanes load the same addresses -> broadcast.
    float qx[QPW], qy[QPW], qz[QPW], sq[QPW];
#pragma unroll
    for (int q = 0; q < QPW; ++q) {
        qx[q] = pr[(q0 + q) * 3 + 0];
        qy[q] = pr[(q0 + q) * 3 + 1];
        qz[q] = pr[(q0 + q) * 3 + 2];
        sq[q] = qx[q] * qx[q] + qy[q] * qy[q] + qz[q] * qz[q];
    }

    // Four warp-distributed sorted top-16 lists: for query q, lane l (l<16)
    // holds the (l+1)-th smallest d2 seen so far. thr[q] = running 16th-smallest.
    float kd[QPW], thr[QPW];
    int   ki[QPW];
#pragma unroll
    for (int q = 0; q < QPW; ++q) { kd[q] = CUDART_INF_F; ki[q] = -1; thr[q] = CUDART_INF_F; }

    for (int t0 = 0; t0 < NQ; t0 += TILE) {
        __syncthreads();
        // Cooperative tile load: 2048 points, 8 per thread; precompute sq.
        for (int i = tid; i < TILE; i += BLOCK) {
            int   m = t0 + i;
            float x = pr[m * 3 + 0];
            float y = pr[m * 3 + 1];
            float z = pr[m * 3 + 2];
            tile[i] = make_float4(x, y, z, x * x + y * y + z * z);
        }
        __syncthreads();

        for (int s = 0; s < TILE; s += 32) {
            const int    sg = t0 + s;            // global index of lane-0 candidate
            const float4 c  = tile[s + lane];
            float d[QPW];
#pragma unroll
            for (int q = 0; q < QPW; ++q) {
                float dot = fmaf(qx[q], c.x, fmaf(qy[q], c.y, qz[q] * c.z));
                d[q] = fmaf(-2.0f, dot, sq[q] + c.w);   // sq_n + sq_m - 2*dot
            }
            // Self-exclusion (queries are consecutive; rare warp-uniform branch)
            if ((unsigned)(q0 + QPW - 1 - sg) < (unsigned)(32 + QPW - 1)) {
#pragma unroll
                for (int q = 0; q < QPW; ++q) {
                    int rel = q0 + q - sg;
                    if ((unsigned)rel < 32u && lane == rel) d[q] = CUDART_INF_F;
                }
            }

            // Skip the whole insert block when no query qualifies this step.
            bool any = false;
#pragma unroll
            for (int q = 0; q < QPW; ++q) any |= (d[q] < thr[q]);
            if (__ballot_sync(FULL, any)) {
#pragma unroll
                for (int q = 0; q < QPW; ++q) {
                    unsigned mq = __ballot_sync(FULL, d[q] < thr[q]);
                    while (mq) {
                        // Lowest lane first == ascending candidate index (tie
                        // stability, matches top_k).
                        const int   src = __ffs(mq) - 1;
                        const float v   = __shfl_sync(FULL, d[q], src);
                        const int   vi  = sg + src;
                        // Stable insert: after all existing elements <= v.
                        const unsigned le  = __ballot_sync(FULL, (lane < KNN) && (kd[q] <= v));
                        const int      pos = __popc(le);
                        const float kdu = __shfl_up_sync(FULL, kd[q], 1);
                        const int   kiu = __shfl_up_sync(FULL, ki[q], 1);
                        if (lane >= pos) {
                            kd[q] = (lane == pos) ? v  : kdu;
                            ki[q] = (lane == pos) ? vi : kiu;
                        }
                        thr[q] = __shfl_sync(FULL, kd[q], KNN - 1);
                        mq &= mq - 1;
                        mq &= __ballot_sync(FULL, d[q] < thr[q]);  // re-filter
                    }
                }
            }
        }
    }

    // ---- Edge lengths + L1: lanes 0..15 hold one neighbor per query ----
    float partial = 0.0f;
    if (lane < KNN) {
#pragma unroll
        for (int q = 0; q < QPW; ++q) {
            const int nb = ki[q];
            float rx = pr[nb * 3 + 0] - qx[q];
            float ry = pr[nb * 3 + 1] - qy[q];
            float rz = pr[nb * 3 + 2] - qz[q];
            float dref = sqrtf(rx * rx + ry * ry + rz * rz);
            float pqx = pp[(q0 + q) * 3 + 0];
            float pqy = pp[(q0 + q) * 3 + 1];
            float pqz = pp[(q0 + q) * 3 + 2];
            float px = pp[nb * 3 + 0] - pqx;
            float py = pp[nb * 3 + 1] - pqy;
            float pz = pp[nb * 3 + 2] - pqz;
            float dprd = sqrtf(px * px + py * py + pz * pz);
            partial += fabsf(dref - dprd);
        }
    }

    // Deterministic warp + block reduction
#pragma unroll
    for (int o = 16; o > 0; o >>= 1)
        partial += __shfl_xor_sync(FULL, partial, o);
    if (lane == 0) wsum[wid] = partial;
    __syncthreads();

    if (wid == 0) {
        float s = (lane < WPB) ? wsum[lane] : 0.0f;
#pragma unroll
        for (int o = 16; o > 0; o >>= 1)
            s += __shfl_xor_sync(FULL, s, o);
        if (lane == 0) g_partials[blockIdx.x] = s;
    }
}

__global__ void finalize_kernel(float* __restrict__ out)
{
    __shared__ double sred[256];
    int t = threadIdx.x;
    double s = 0.0;
    for (int i = t; i < NBLK; i += 256) s += (double)g_partials[i];
    sred[t] = s;
    __syncthreads();
#pragma unroll
    for (int st = 128; st > 0; st >>= 1) {
        if (t < st) sred[t] += sred[t + st];
        __syncthreads();
    }
    if (t == 0) out[0] = (float)(sred[0] / TOTAL_EDGES);
}

extern "C" void kernel_launch(void* const* d_in, const int* in_sizes, int n_in,
                              void* d_out, int out_size)
{
    (void)in_sizes; (void)n_in; (void)out_size;
    const float* points_ref = (const float*)d_in[0];
    const float* points     = (const float*)d_in[1];
    knn_loss_kernel<<<NBLK, BLOCK>>>(points_ref, points);
    finalize_kernel<<<1, 256>>>((float*)d_out);
}

// round 8
// speedup vs baseline: 1.5188x; 1.5188x over previous
#include <cuda_runtime.h>
#include <math_constants.h>

// Problem constants
#define BQ    2
#define NQ    8192
#define KNN   16
#define WPB   16                       // warps (queries) per block
#define BLOCK (WPB * 32)               // 512 threads
#define TILE  2048                     // candidates per smem tile (32 KB of float4)
#define BLOCKS_PER_BATCH (NQ / WPB)    // 512
#define NBLK  (BQ * BLOCKS_PER_BATCH)  // 1024
#define FULL  0xffffffffu
#define TOTAL_EDGES ((double)(BQ) * (double)(NQ) * (double)(KNN))

// Deterministic per-block partial sums (no atomics -> same result every replay)
__device__ float g_partials[NBLK];

// Stable insert of (v, vi) into the warp-distributed sorted top-16
// (lane l < 16 holds the (l+1)-th smallest). Stale values (v >= current 16th)
// produce pos==16 and become no-ops for lanes < 16. Ties keep the earlier
// (lower-index) element first -> matches jax.lax.top_k stability.
#define INSERT_EVENT(v, vi)                                                   \
    do {                                                                      \
        const unsigned le_ = __ballot_sync(FULL, (lane < KNN) && (kd <= (v)));\
        const int pos_ = __popc(le_);                                         \
        const float kdu_ = __shfl_up_sync(FULL, kd, 1);                       \
        const int   kiu_ = __shfl_up_sync(FULL, ki, 1);                       \
        if (lane >= pos_) {                                                   \
            kd = (lane == pos_) ? (v)  : kdu_;                                \
            ki = (lane == pos_) ? (vi) : kiu_;                                \
        }                                                                     \
        thr = __shfl_sync(FULL, kd, KNN - 1);                                 \
    } while (0)

__global__ __launch_bounds__(BLOCK)
void knn_loss_kernel(const float* __restrict__ points_ref,
                     const float* __restrict__ points)
{
    __shared__ float4 tile[TILE];      // (x, y, z, x^2+y^2+z^2)
    __shared__ float  wsum[WPB];

    const int tid  = threadIdx.x;
    const int wid  = tid >> 5;
    const int lane = tid & 31;
    const int b    = blockIdx.x / BLOCKS_PER_BATCH;
    const int qn   = (blockIdx.x % BLOCKS_PER_BATCH) * WPB + wid;  // this warp's query

    const float* __restrict__ pr = points_ref + (size_t)b * NQ * 3;
    const float* __restrict__ pp = points     + (size_t)b * NQ * 3;

    // Query point (ref cloud) + squared norm (same expansion as reference)
    const float qx  = pr[qn * 3 + 0];
    const float qy  = pr[qn * 3 + 1];
    const float qz  = pr[qn * 3 + 2];
    const float sqn = qx * qx + qy * qy + qz * qz;

    // Warp-distributed sorted top-16
    float kd  = CUDART_INF_F;
    int   ki  = -1;
    float thr = CUDART_INF_F;

    for (int t0 = 0; t0 < NQ; t0 += TILE) {
        __syncthreads();
        // Cooperative tile load: 2048 points, 4 per thread; precompute sq.
        for (int i = tid; i < TILE; i += BLOCK) {
            int   m = t0 + i;
            float x = pr[m * 3 + 0];
            float y = pr[m * 3 + 1];
            float z = pr[m * 3 + 2];
            tile[i] = make_float4(x, y, z, x * x + y * y + z * z);
        }
        __syncthreads();

        // 64 candidates per step, one early-out ballot per step.
        for (int s = 0; s < TILE; s += 64) {
            const int    sg = t0 + s;
            const float4 c0 = tile[s + lane];
            const float4 c1 = tile[s + 32 + lane];
            float dot0 = fmaf(qx, c0.x, fmaf(qy, c0.y, qz * c0.z));
            float dot1 = fmaf(qx, c1.x, fmaf(qy, c1.y, qz * c1.z));
            float d0 = fmaf(-2.0f, dot0, sqn + c0.w);   // sq_n + sq_m - 2*dot
            float d1 = fmaf(-2.0f, dot1, sqn + c1.w);

            // Self-exclusion (rare warp-uniform branch)
            const unsigned rel = (unsigned)(qn - sg);
            if (rel < 64u) {
                if (lane == (int)(rel & 31u)) {
                    if (rel < 32u) d0 = CUDART_INF_F; else d1 = CUDART_INF_F;
                }
            }

            if (__ballot_sync(FULL, (d0 < thr) | (d1 < thr))) {
                // Ascending candidate order: all of d0's lanes, then d1's.
                unsigned m0 = __ballot_sync(FULL, d0 < thr);
                while (m0) {
                    const int   src = __ffs(m0) - 1;
                    const float v   = __shfl_sync(FULL, d0, src);
                    INSERT_EVENT(v, sg + src);          // index affine in lane
                    m0 &= m0 - 1;
                }
                unsigned m1 = __ballot_sync(FULL, d1 < thr);
                while (m1) {
                    const int   src = __ffs(m1) - 1;
                    const float v   = __shfl_sync(FULL, d1, src);
                    INSERT_EVENT(v, sg + 32 + src);
                    m1 &= m1 - 1;
                }
            }
        }
    }

    // ---- Edge lengths + L1: lanes 0..15 each handle one neighbor ----
    const float pqx = pp[qn * 3 + 0];
    const float pqy = pp[qn * 3 + 1];
    const float pqz = pp[qn * 3 + 2];

    float partial = 0.0f;
    if (lane < KNN) {
        const int nb = ki;
        float rx = pr[nb * 3 + 0] - qx;
        float ry = pr[nb * 3 + 1] - qy;
        float rz = pr[nb * 3 + 2] - qz;
        float dref = sqrtf(rx * rx + ry * ry + rz * rz);
        float px = pp[nb * 3 + 0] - pqx;
        float py = pp[nb * 3 + 1] - pqy;
        float pz = pp[nb * 3 + 2] - pqz;
        float dprd = sqrtf(px * px + py * py + pz * pz);
        partial = fabsf(dref - dprd);
    }

    // Deterministic warp + block reduction
#pragma unroll
    for (int o = 16; o > 0; o >>= 1)
        partial += __shfl_xor_sync(FULL, partial, o);
    if (lane == 0) wsum[wid] = partial;
    __syncthreads();

    if (wid == 0) {
        float s = (lane < WPB) ? wsum[lane] : 0.0f;
#pragma unroll
        for (int o = 16; o > 0; o >>= 1)
            s += __shfl_xor_sync(FULL, s, o);
        if (lane == 0) g_partials[blockIdx.x] = s;
    }
}

__global__ void finalize_kernel(float* __restrict__ out)
{
    __shared__ double sred[256];
    int t = threadIdx.x;
    double s = 0.0;
    for (int i = t; i < NBLK; i += 256) s += (double)g_partials[i];
    sred[t] = s;
    __syncthreads();
#pragma unroll
    for (int st = 128; st > 0; st >>= 1) {
        if (t < st) sred[t] += sred[t + st];
        __syncthreads();
    }
    if (t == 0) out[0] = (float)(sred[0] / TOTAL_EDGES);
}

extern "C" void kernel_launch(void* const* d_in, const int* in_sizes, int n_in,
                              void* d_out, int out_size)
{
    (void)in_sizes; (void)n_in; (void)out_size;
    const float* points_ref = (const float*)d_in[0];
    const float* points     = (const float*)d_in[1];
    knn_loss_kernel<<<NBLK, BLOCK>>>(points_ref, points);
    finalize_kernel<<<1, 256>>>((float*)d_out);
}

// round 9
// speedup vs baseline: 1.5246x; 1.0038x over previous
#include <cuda_runtime.h>
#include <math_constants.h>

// Problem constants
#define BQ    2
#define NQ    8192
#define KNN   16
#define QPW   2                        // queries per warp
#define WPB   16                       // warps per block
#define BLOCK 512
#define QPB   (QPW * WPB)              // 32 queries per block
#define TILE  2048                     // candidates per smem tile (32 KB of float4)
#define BLOCKS_PER_BATCH (NQ / QPB)    // 256
#define NBLK  (BQ * BLOCKS_PER_BATCH)  // 512
#define FULL  0xffffffffu
#define TOTAL_EDGES ((double)(BQ) * (double)(NQ) * (double)(KNN))

// Deterministic per-block partial sums (no atomics -> same result every replay)
__device__ float g_partials[NBLK];

// Stable insert of (v, vi) into a warp-distributed sorted top-16
// (lane l < 16 holds the (l+1)-th smallest). Stale values (v >= current 16th)
// give pos==16 -> no-op for lanes < 16. Ties keep the earlier (lower-index)
// element first -> matches jax.lax.top_k stability.
__device__ __forceinline__ void insert_event(float v, int vi, int lane,
                                             float& kd, int& ki, float& thr)
{
    const unsigned le  = __ballot_sync(FULL, (lane < KNN) && (kd <= v));
    const int      pos = __popc(le);
    const float kdu = __shfl_up_sync(FULL, kd, 1);
    const int   kiu = __shfl_up_sync(FULL, ki, 1);
    if (lane >= pos) {
        kd = (lane == pos) ? v  : kdu;
        ki = (lane == pos) ? vi : kiu;
    }
    thr = __shfl_sync(FULL, kd, KNN - 1);
}

__global__ __launch_bounds__(BLOCK)
void knn_loss_kernel(const float* __restrict__ points_ref,
                     const float* __restrict__ points)
{
    __shared__ float4 tile[TILE];      // (x, y, z, x^2+y^2+z^2)
    __shared__ float  wsum[WPB];

    const int tid  = threadIdx.x;
    const int wid  = tid >> 5;
    const int lane = tid & 31;
    const int b    = blockIdx.x / BLOCKS_PER_BATCH;
    const int q0   = (blockIdx.x % BLOCKS_PER_BATCH) * QPB + wid * QPW; // first of 2 queries

    const float* __restrict__ pr = points_ref + (size_t)b * NQ * 3;
    const float* __restrict__ pp = points     + (size_t)b * NQ * 3;

    // Query points (ref cloud) + squared norms (same expansion as reference).
    float qx[QPW], qy[QPW], qz[QPW], sq[QPW];
#pragma unroll
    for (int q = 0; q < QPW; ++q) {
        qx[q] = pr[(q0 + q) * 3 + 0];
        qy[q] = pr[(q0 + q) * 3 + 1];
        qz[q] = pr[(q0 + q) * 3 + 2];
        sq[q] = qx[q] * qx[q] + qy[q] * qy[q] + qz[q] * qz[q];
    }

    // Per-query warp-distributed sorted top-16
    float kd[QPW], thr[QPW];
    int   ki[QPW];
#pragma unroll
    for (int q = 0; q < QPW; ++q) { kd[q] = CUDART_INF_F; ki[q] = -1; thr[q] = CUDART_INF_F; }

    for (int t0 = 0; t0 < NQ; t0 += TILE) {
        __syncthreads();
        // Cooperative tile load: 2048 points, 4 per thread; precompute sq.
        for (int i = tid; i < TILE; i += BLOCK) {
            int   m = t0 + i;
            float x = pr[m * 3 + 0];
            float y = pr[m * 3 + 1];
            float z = pr[m * 3 + 2];
            tile[i] = make_float4(x, y, z, x * x + y * y + z * z);
        }
        __syncthreads();

        // 64 candidates x 2 queries per step; one early-out ballot per step.
        for (int s = 0; s < TILE; s += 64) {
            const int    sg = t0 + s;
            const float4 c0 = tile[s + lane];
            const float4 c1 = tile[s + 32 + lane];
            float d0[QPW], d1[QPW];
#pragma unroll
            for (int q = 0; q < QPW; ++q) {
                float dot0 = fmaf(qx[q], c0.x, fmaf(qy[q], c0.y, qz[q] * c0.z));
                float dot1 = fmaf(qx[q], c1.x, fmaf(qy[q], c1.y, qz[q] * c1.z));
                d0[q] = fmaf(-2.0f, dot0, sq[q] + c0.w);   // sq_n + sq_m - 2*dot
                d1[q] = fmaf(-2.0f, dot1, sq[q] + c1.w);
            }

            // Self-exclusion (rare warp-uniform branch; queries consecutive)
            if ((unsigned)(q0 + QPW - 1 - sg) < (unsigned)(64 + QPW - 1)) {
#pragma unroll
                for (int q = 0; q < QPW; ++q) {
                    const unsigned rel = (unsigned)(q0 + q - sg);
                    if (rel < 64u && lane == (int)(rel & 31u)) {
                        if (rel < 32u) d0[q] = CUDART_INF_F;
                        else           d1[q] = CUDART_INF_F;
                    }
                }
            }

            bool any = false;
#pragma unroll
            for (int q = 0; q < QPW; ++q)
                any |= (d0[q] < thr[q]) | (d1[q] < thr[q]);
            if (__ballot_sync(FULL, any)) {
#pragma unroll
                for (int q = 0; q < QPW; ++q) {
                    // Ascending candidate order within each query (stability).
                    unsigned m0 = __ballot_sync(FULL, d0[q] < thr[q]);
                    while (m0) {
                        const int   src = __ffs(m0) - 1;
                        const float v   = __shfl_sync(FULL, d0[q], src);
                        insert_event(v, sg + src, lane, kd[q], ki[q], thr[q]);
                        m0 &= m0 - 1;
                    }
                    unsigned m1 = __ballot_sync(FULL, d1[q] < thr[q]);
                    while (m1) {
                        const int   src = __ffs(m1) - 1;
                        const float v   = __shfl_sync(FULL, d1[q], src);
                        insert_event(v, sg + 32 + src, lane, kd[q], ki[q], thr[q]);
                        m1 &= m1 - 1;
                    }
                }
            }
        }
    }

    // ---- Edge lengths + L1: lanes 0..15 hold one neighbor per query ----
    float partial = 0.0f;
    if (lane < KNN) {
#pragma unroll
        for (int q = 0; q < QPW; ++q) {
            const int nb = ki[q];
            float rx = pr[nb * 3 + 0] - qx[q];
            float ry = pr[nb * 3 + 1] - qy[q];
            float rz = pr[nb * 3 + 2] - qz[q];
            float dref = sqrtf(rx * rx + ry * ry + rz * rz);
            float pqx = pp[(q0 + q) * 3 + 0];
            float pqy = pp[(q0 + q) * 3 + 1];
            float pqz = pp[(q0 + q) * 3 + 2];
            float px = pp[nb * 3 + 0] - pqx;
            float py = pp[nb * 3 + 1] - pqy;
            float pz = pp[nb * 3 + 2] - pqz;
            float dprd = sqrtf(px * px + py * py + pz * pz);
            partial += fabsf(dref - dprd);
        }
    }

    // Deterministic warp + block reduction
#pragma unroll
    for (int o = 16; o > 0; o >>= 1)
        partial += __shfl_xor_sync(FULL, partial, o);
    if (lane == 0) wsum[wid] = partial;
    __syncthreads();

    if (wid == 0) {
        float s = (lane < WPB) ? wsum[lane] : 0.0f;
#pragma unroll
        for (int o = 16; o > 0; o >>= 1)
            s += __shfl_xor_sync(FULL, s, o);
        if (lane == 0) g_partials[blockIdx.x] = s;
    }
}

__global__ void finalize_kernel(float* __restrict__ out)
{
    __shared__ double sred[256];
    int t = threadIdx.x;
    double s = 0.0;
    for (int i = t; i < NBLK; i += 256) s += (double)g_partials[i];
    sred[t] = s;
    __syncthreads();
#pragma unroll
    for (int st = 128; st > 0; st >>= 1) {
        if (t < st) sred[t] += sred[t + st];
        __syncthreads();
    }
    if (t == 0) out[0] = (float)(sred[0] / TOTAL_EDGES);
}

extern "C" void kernel_launch(void* const* d_in, const int* in_sizes, int n_in,
                              void* d_out, int out_size)
{
    (void)in_sizes; (void)n_in; (void)out_size;
    const float* points_ref = (const float*)d_in[0];
    const float* points     = (const float*)d_in[1];
    knn_loss_kernel<<<NBLK, BLOCK>>>(points_ref, points);
    finalize_kernel<<<1, 256>>>((float*)d_out);
}

// round 10
// speedup vs baseline: 1.8708x; 1.2271x over previous
#include <cuda_runtime.h>
#include <math_constants.h>

// Problem constants
#define BQ    2
#define NQ    8192
#define KNN   16
#define QPW   2                        // queries per warp
#define WPB   16                       // warps per block
#define BLOCK 512
#define QPB   (QPW * WPB)              // 32 queries per block
#define TILE  2048                     // candidates per smem tile (32 KB of float4)
#define BLOCKS_PER_BATCH (NQ / QPB)    // 256
#define NBLK  (BQ * BLOCKS_PER_BATCH)  // 512
#define FULL  0xffffffffu
#define TOTAL_EDGES ((double)(BQ) * (double)(NQ) * (double)(KNN))

// Deterministic per-block partial sums (no atomics -> same result every replay)
__device__ float g_partials[NBLK];

// Stable insert of (v, vi) into a warp-distributed sorted top-16
// (lane l < 16 holds the (l+1)-th smallest). Stale values (v >= current 16th)
// give pos==16 -> no-op for lanes < 16. Ties keep the earlier (lower-index)
// element first -> matches jax.lax.top_k stability. No thr update here.
__device__ __forceinline__ void insert_event(float v, int vi, int lane,
                                             float& kd, int& ki)
{
    const unsigned le  = __ballot_sync(FULL, (lane < KNN) && (kd <= v));
    const int      pos = __popc(le);
    const float kdu = __shfl_up_sync(FULL, kd, 1);
    const int   kiu = __shfl_up_sync(FULL, ki, 1);
    if (lane >= pos) {
        kd = (lane == pos) ? v  : kdu;
        ki = (lane == pos) ? vi : kiu;
    }
}

__global__ __launch_bounds__(BLOCK)
void knn_loss_kernel(const float* __restrict__ points_ref,
                     const float* __restrict__ points)
{
    __shared__ float4 tile[TILE];      // (x, y, z, x^2+y^2+z^2)
    __shared__ float  wsum[WPB];

    const int tid  = threadIdx.x;
    const int wid  = tid >> 5;
    const int lane = tid & 31;
    const int b    = blockIdx.x / BLOCKS_PER_BATCH;
    const int q0   = (blockIdx.x % BLOCKS_PER_BATCH) * QPB + wid * QPW; // first of 2 queries

    const float* __restrict__ pr = points_ref + (size_t)b * NQ * 3;
    const float* __restrict__ pp = points     + (size_t)b * NQ * 3;

    // Query points (ref cloud) + squared norms (same expansion as reference).
    float qx[QPW], qy[QPW], qz[QPW], sq[QPW];
#pragma unroll
    for (int q = 0; q < QPW; ++q) {
        qx[q] = pr[(q0 + q) * 3 + 0];
        qy[q] = pr[(q0 + q) * 3 + 1];
        qz[q] = pr[(q0 + q) * 3 + 2];
        sq[q] = qx[q] * qx[q] + qy[q] * qy[q] + qz[q] * qz[q];
    }

    // Per-query warp-distributed sorted top-16
    float kd[QPW], thr[QPW];
    int   ki[QPW];
#pragma unroll
    for (int q = 0; q < QPW; ++q) { kd[q] = CUDART_INF_F; ki[q] = -1; thr[q] = CUDART_INF_F; }

    for (int t0 = 0; t0 < NQ; t0 += TILE) {
        __syncthreads();
        // Cooperative tile load: 2048 points, 4 per thread; precompute sq.
        for (int i = tid; i < TILE; i += BLOCK) {
            int   m = t0 + i;
            float x = pr[m * 3 + 0];
            float y = pr[m * 3 + 1];
            float z = pr[m * 3 + 2];
            tile[i] = make_float4(x, y, z, x * x + y * y + z * z);
        }
        __syncthreads();

        if (t0 == 0) {
            // ---- Warm start: vote-free min-scan of tile 0 ----
            float mn[QPW];
#pragma unroll
            for (int q = 0; q < QPW; ++q) mn[q] = CUDART_INF_F;
            for (int s = 0; s < TILE; s += 64) {
                const int    sg = s;
                const float4 c0 = tile[s + lane];
                const float4 c1 = tile[s + 32 + lane];
#pragma unroll
                for (int q = 0; q < QPW; ++q) {
                    float dot0 = fmaf(qx[q], c0.x, fmaf(qy[q], c0.y, qz[q] * c0.z));
                    float dot1 = fmaf(qx[q], c1.x, fmaf(qy[q], c1.y, qz[q] * c1.z));
                    float d0 = fmaf(-2.0f, dot0, sq[q] + c0.w);
                    float d1 = fmaf(-2.0f, dot1, sq[q] + c1.w);
                    const unsigned rel0 = (unsigned)(q0 + q - sg);
                    if (rel0 < 64u && lane == (int)(rel0 & 31u)) {
                        if (rel0 < 32u) d0 = CUDART_INF_F; else d1 = CUDART_INF_F;
                    }
                    mn[q] = fminf(mn[q], fminf(d0, d1));
                }
            }
            // Bitonic sort of the 32 per-lane minima (ascending); lane 15 value
            // T is an upper bound on the true 16th-NN d2 (16 lanes -> 16
            // distinct non-self candidates <= T). Network validated in R5.
#pragma unroll
            for (int k = 2; k <= 32; k <<= 1) {
#pragma unroll
                for (int j = k >> 1; j >= 1; j >>= 1) {
                    bool up = ((lane & k) == 0);
                    bool tm = (up == ((lane & j) == 0));
#pragma unroll
                    for (int q = 0; q < QPW; ++q) {
                        float o = __shfl_xor_sync(FULL, mn[q], j);
                        mn[q] = tm ? fminf(mn[q], o) : fmaxf(mn[q], o);
                    }
                }
            }
#pragma unroll
            for (int q = 0; q < QPW; ++q) {
                float T = __shfl_sync(FULL, mn[q], KNN - 1);
                // nextafter-up so strict-< filter admits candidates with d2 == T
                thr[q] = __int_as_float(__float_as_int(T) + 1);
            }
        }

        // ---- Filtered scan: 64 candidates x 2 queries per step ----
        for (int s = 0; s < TILE; s += 64) {
            const int    sg = t0 + s;
            const float4 c0 = tile[s + lane];
            const float4 c1 = tile[s + 32 + lane];
            float d0[QPW], d1[QPW];
#pragma unroll
            for (int q = 0; q < QPW; ++q) {
                float dot0 = fmaf(qx[q], c0.x, fmaf(qy[q], c0.y, qz[q] * c0.z));
                float dot1 = fmaf(qx[q], c1.x, fmaf(qy[q], c1.y, qz[q] * c1.z));
                d0[q] = fmaf(-2.0f, dot0, sq[q] + c0.w);   // sq_n + sq_m - 2*dot
                d1[q] = fmaf(-2.0f, dot1, sq[q] + c1.w);
            }

            // Self-exclusion (rare warp-uniform branch; queries consecutive)
            if ((unsigned)(q0 + QPW - 1 - sg) < (unsigned)(64 + QPW - 1)) {
#pragma unroll
                for (int q = 0; q < QPW; ++q) {
                    const unsigned rel = (unsigned)(q0 + q - sg);
                    if (rel < 64u && lane == (int)(rel & 31u)) {
                        if (rel < 32u) d0[q] = CUDART_INF_F;
                        else           d1[q] = CUDART_INF_F;
                    }
                }
            }

            bool any = false;
#pragma unroll
            for (int q = 0; q < QPW; ++q)
                any |= (d0[q] < thr[q]) | (d1[q] < thr[q]);
            if (__ballot_sync(FULL, any)) {
#pragma unroll
                for (int q = 0; q < QPW; ++q) {
                    // Ascending candidate order within each query (stability).
                    unsigned m0 = __ballot_sync(FULL, d0[q] < thr[q]);
                    while (m0) {
                        const int   src = __ffs(m0) - 1;
                        const float v   = __shfl_sync(FULL, d0[q], src);
                        insert_event(v, sg + src, lane, kd[q], ki[q]);
                        m0 &= m0 - 1;
                    }
                    unsigned m1 = __ballot_sync(FULL, d1[q] < thr[q]);
                    while (m1) {
                        const int   src = __ffs(m1) - 1;
                        const float v   = __shfl_sync(FULL, d1[q], src);
                        insert_event(v, sg + 32 + src, lane, kd[q], ki[q]);
                        m1 &= m1 - 1;
                    }
                    // Refresh threshold once per hit-step (can only tighten).
                    thr[q] = fminf(thr[q], __shfl_sync(FULL, kd[q], KNN - 1));
                }
            }
        }
    }

    // ---- Edge lengths + L1: lanes 0..15 hold one neighbor per query ----
    float partial = 0.0f;
    if (lane < KNN) {
#pragma unroll
        for (int q = 0; q < QPW; ++q) {
            const int nb = ki[q];
            float rx = pr[nb * 3 + 0] - qx[q];
            float ry = pr[nb * 3 + 1] - qy[q];
            float rz = pr[nb * 3 + 2] - qz[q];
            float dref = sqrtf(rx * rx + ry * ry + rz * rz);
            float pqx = pp[(q0 + q) * 3 + 0];
            float pqy = pp[(q0 + q) * 3 + 1];
            float pqz = pp[(q0 + q) * 3 + 2];
            float px = pp[nb * 3 + 0] - pqx;
            float py = pp[nb * 3 + 1] - pqy;
            float pz = pp[nb * 3 + 2] - pqz;
            float dprd = sqrtf(px * px + py * py + pz * pz);
            partial += fabsf(dref - dprd);
        }
    }

    // Deterministic warp + block reduction
#pragma unroll
    for (int o = 16; o > 0; o >>= 1)
        partial += __shfl_xor_sync(FULL, partial, o);
    if (lane == 0) wsum[wid] = partial;
    __syncthreads();

    if (wid == 0) {
        float s = (lane < WPB) ? wsum[lane] : 0.0f;
#pragma unroll
        for (int o = 16; o > 0; o >>= 1)
            s += __shfl_xor_sync(FULL, s, o);
        if (lane == 0) g_partials[blockIdx.x] = s;
    }
}

__global__ void finalize_kernel(float* __restrict__ out)
{
    __shared__ double sred[256];
    int t = threadIdx.x;
    double s = 0.0;
    for (int i = t; i < NBLK; i += 256) s += (double)g_partials[i];
    sred[t] = s;
    __syncthreads();
#pragma unroll
    for (int st = 128; st > 0; st >>= 1) {
        if (t < st) sred[t] += sred[t + st];
        __syncthreads();
    }
    if (t == 0) out[0] = (float)(sred[0] / TOTAL_EDGES);
}

// Launch-parity padding: with 4 launches per kernel_launch call, ncu's
// "-s 5 -c 1" lands on the MAIN kernel (global launch idx 5 = 2nd launch of
// the 2nd call) instead of finalize_kernel. Costs ~2 graph nodes of overhead.
__global__ void pad_kernel() {}

extern "C" void kernel_launch(void* const* d_in, const int* in_sizes, int n_in,
                              void* d_out, int out_size)
{
    (void)in_sizes; (void)n_in; (void)out_size;
    const float* points_ref = (const float*)d_in[0];
    const float* points     = (const float*)d_in[1];
    pad_kernel<<<1, 32>>>();
    knn_loss_kernel<<<NBLK, BLOCK>>>(points_ref, points);
    finalize_kernel<<<1, 256>>>((float*)d_out);
    pad_kernel<<<1, 32>>>();
}

// round 11
// speedup vs baseline: 1.8719x; 1.0006x over previous
#include <cuda_runtime.h>
#include <math_constants.h>

// Problem constants
#define BQ    2
#define NQ    8192
#define KNN   16
#define QPW   2                        // queries per warp
#define WPB   16                       // warps per block
#define BLOCK 512
#define QPB   (QPW * WPB)              // 32 queries per block
#define TILE  2048                     // candidates per smem tile (32 KB of float4)
#define BLOCKS_PER_BATCH (NQ / QPB)    // 256
#define NBLK  (BQ * BLOCKS_PER_BATCH)  // 512
#define FULL  0xffffffffu
#define TOTAL_EDGES ((double)(BQ) * (double)(NQ) * (double)(KNN))

// Deterministic per-block partial sums (no atomics -> same result every replay)
__device__ float g_partials[NBLK];

// ---- packed f32x2 helpers (each half is IEEE-RN, bit-identical to scalar) ----
typedef unsigned long long u64;
__device__ __forceinline__ u64 pack2(float lo, float hi) {
    u64 r;
    asm("mov.b64 %0, {%1, %2};" : "=l"(r)
        : "r"(__float_as_uint(lo)), "r"(__float_as_uint(hi)));
    return r;
}
__device__ __forceinline__ void unpack2(u64 v, float& lo, float& hi) {
    unsigned a, b;
    asm("mov.b64 {%0, %1}, %2;" : "=r"(a), "=r"(b) : "l"(v));
    lo = __uint_as_float(a); hi = __uint_as_float(b);
}
__device__ __forceinline__ u64 fma2(u64 a, u64 b, u64 c) {
    u64 r; asm("fma.rn.f32x2 %0, %1, %2, %3;" : "=l"(r) : "l"(a), "l"(b), "l"(c));
    return r;
}
__device__ __forceinline__ u64 mul2(u64 a, u64 b) {
    u64 r; asm("mul.rn.f32x2 %0, %1, %2;" : "=l"(r) : "l"(a), "l"(b));
    return r;
}
__device__ __forceinline__ u64 add2(u64 a, u64 b) {
    u64 r; asm("add.rn.f32x2 %0, %1, %2;" : "=l"(r) : "l"(a), "l"(b));
    return r;
}

// Stable insert of (v, vi) into a warp-distributed sorted top-16
// (lane l < 16 holds the (l+1)-th smallest). Stale values (v >= current 16th)
// give pos==16 -> no-op for lanes < 16. Ties keep the earlier (lower-index)
// element first -> matches jax.lax.top_k stability. No thr update here.
__device__ __forceinline__ void insert_event(float v, int vi, int lane,
                                             float& kd, int& ki)
{
    const unsigned le  = __ballot_sync(FULL, (lane < KNN) && (kd <= v));
    const int      pos = __popc(le);
    const float kdu = __shfl_up_sync(FULL, kd, 1);
    const int   kiu = __shfl_up_sync(FULL, ki, 1);
    if (lane >= pos) {
        kd = (lane == pos) ? v  : kdu;
        ki = (lane == pos) ? vi : kiu;
    }
}

__global__ __launch_bounds__(BLOCK)
void knn_loss_kernel(const float* __restrict__ points_ref,
                     const float* __restrict__ points)
{
    __shared__ float4 tile[TILE];      // (x, y, z, x^2+y^2+z^2)
    __shared__ float  wsum[WPB];

    const int tid  = threadIdx.x;
    const int wid  = tid >> 5;
    const int lane = tid & 31;
    const int b    = blockIdx.x / BLOCKS_PER_BATCH;
    const int q0   = (blockIdx.x % BLOCKS_PER_BATCH) * QPB + wid * QPW; // first of 2 queries

    const float* __restrict__ pr = points_ref + (size_t)b * NQ * 3;
    const float* __restrict__ pp = points     + (size_t)b * NQ * 3;

    // Query points (ref cloud) + squared norms (same expansion as reference).
    float qx[QPW], qy[QPW], qz[QPW], sq[QPW];
    u64 Qx[QPW], Qy[QPW], Qz[QPW], S2[QPW];
#pragma unroll
    for (int q = 0; q < QPW; ++q) {
        qx[q] = pr[(q0 + q) * 3 + 0];
        qy[q] = pr[(q0 + q) * 3 + 1];
        qz[q] = pr[(q0 + q) * 3 + 2];
        sq[q] = qx[q] * qx[q] + qy[q] * qy[q] + qz[q] * qz[q];
        Qx[q] = pack2(qx[q], qx[q]);
        Qy[q] = pack2(qy[q], qy[q]);
        Qz[q] = pack2(qz[q], qz[q]);
        S2[q] = pack2(sq[q], sq[q]);
    }
    const u64 N2 = pack2(-2.0f, -2.0f);

    // Per-query warp-distributed sorted top-16
    float kd[QPW], thr[QPW];
    int   ki[QPW];
#pragma unroll
    for (int q = 0; q < QPW; ++q) { kd[q] = CUDART_INF_F; ki[q] = -1; thr[q] = CUDART_INF_F; }

    for (int t0 = 0; t0 < NQ; t0 += TILE) {
        __syncthreads();
        // Cooperative tile load: 2048 points, 4 per thread; precompute sq.
        for (int i = tid; i < TILE; i += BLOCK) {
            int   m = t0 + i;
            float x = pr[m * 3 + 0];
            float y = pr[m * 3 + 1];
            float z = pr[m * 3 + 2];
            tile[i] = make_float4(x, y, z, x * x + y * y + z * z);
        }
        __syncthreads();

        if (t0 == 0) {
            // ---- Warm start: vote-free min-scan of tile 0 (packed math) ----
            float mn[QPW];
#pragma unroll
            for (int q = 0; q < QPW; ++q) mn[q] = CUDART_INF_F;
            for (int s = 0; s < TILE; s += 64) {
                const float4 c0 = tile[s + lane];
                const float4 c1 = tile[s + 32 + lane];
                const u64 cx = pack2(c0.x, c1.x);
                const u64 cy = pack2(c0.y, c1.y);
                const u64 cz = pack2(c0.z, c1.z);
                const u64 cw = pack2(c0.w, c1.w);
#pragma unroll
                for (int q = 0; q < QPW; ++q) {
                    u64 dA = fma2(N2, fma2(Qx[q], cx, fma2(Qy[q], cy, mul2(Qz[q], cz))),
                                  add2(S2[q], cw));
                    float d0, d1; unpack2(dA, d0, d1);
                    const unsigned rel0 = (unsigned)(q0 + q - s);
                    if (rel0 < 64u && lane == (int)(rel0 & 31u)) {
                        if (rel0 < 32u) d0 = CUDART_INF_F; else d1 = CUDART_INF_F;
                    }
                    mn[q] = fminf(mn[q], fminf(d0, d1));
                }
            }
            // Bitonic sort of the 32 per-lane minima (ascending); lane 15 value
            // T is an upper bound on the true 16th-NN d2 (16 lanes -> 16
            // distinct non-self candidates <= T).
#pragma unroll
            for (int k = 2; k <= 32; k <<= 1) {
#pragma unroll
                for (int j = k >> 1; j >= 1; j >>= 1) {
                    bool up = ((lane & k) == 0);
                    bool tm = (up == ((lane & j) == 0));
#pragma unroll
                    for (int q = 0; q < QPW; ++q) {
                        float o = __shfl_xor_sync(FULL, mn[q], j);
                        mn[q] = tm ? fminf(mn[q], o) : fmaxf(mn[q], o);
                    }
                }
            }
#pragma unroll
            for (int q = 0; q < QPW; ++q) {
                float T = __shfl_sync(FULL, mn[q], KNN - 1);
                // nextafter-up so strict-< filter admits candidates with d2 == T
                thr[q] = __int_as_float(__float_as_int(T) + 1);
            }
        }

        // ---- Filtered scan: 128 candidates x 2 queries per step ----
        for (int s = 0; s < TILE; s += 128) {
            const int    sg = t0 + s;
            const float4 c0 = tile[s + lane];
            const float4 c1 = tile[s + 32 + lane];
            const float4 c2 = tile[s + 64 + lane];
            const float4 c3 = tile[s + 96 + lane];
            const u64 xA = pack2(c0.x, c1.x), yA = pack2(c0.y, c1.y);
            const u64 zA = pack2(c0.z, c1.z), wA = pack2(c0.w, c1.w);
            const u64 xB = pack2(c2.x, c3.x), yB = pack2(c2.y, c3.y);
            const u64 zB = pack2(c2.z, c3.z), wB = pack2(c2.w, c3.w);

            float d0[QPW], d1[QPW], d2[QPW], d3[QPW];
#pragma unroll
            for (int q = 0; q < QPW; ++q) {
                u64 dA = fma2(N2, fma2(Qx[q], xA, fma2(Qy[q], yA, mul2(Qz[q], zA))),
                              add2(S2[q], wA));
                u64 dB = fma2(N2, fma2(Qx[q], xB, fma2(Qy[q], yB, mul2(Qz[q], zB))),
                              add2(S2[q], wB));
                unpack2(dA, d0[q], d1[q]);
                unpack2(dB, d2[q], d3[q]);
            }

            // Self-exclusion (rare warp-uniform branch; queries consecutive)
            if ((unsigned)(q0 + QPW - 1 - sg) < (unsigned)(128 + QPW - 1)) {
#pragma unroll
                for (int q = 0; q < QPW; ++q) {
                    const unsigned rel = (unsigned)(q0 + q - sg);
                    if (rel < 128u && lane == (int)(rel & 31u)) {
                        switch (rel >> 5) {
                            case 0:  d0[q] = CUDART_INF_F; break;
                            case 1:  d1[q] = CUDART_INF_F; break;
                            case 2:  d2[q] = CUDART_INF_F; break;
                            default: d3[q] = CUDART_INF_F; break;
                        }
                    }
                }
            }

            bool any = false;
#pragma unroll
            for (int q = 0; q < QPW; ++q)
                any |= (d0[q] < thr[q]) | (d1[q] < thr[q]) |
                       (d2[q] < thr[q]) | (d3[q] < thr[q]);
            if (__ballot_sync(FULL, any)) {
#pragma unroll
                for (int q = 0; q < QPW; ++q) {
                    // Ascending candidate order within each query (stability).
#pragma unroll
                    for (int u = 0; u < 4; ++u) {
                        const float du = (u == 0) ? d0[q] : (u == 1) ? d1[q]
                                       : (u == 2) ? d2[q] : d3[q];
                        unsigned mu = __ballot_sync(FULL, du < thr[q]);
                        while (mu) {
                            const int   src = __ffs(mu) - 1;
                            const float v   = __shfl_sync(FULL, du, src);
                            insert_event(v, sg + u * 32 + src, lane, kd[q], ki[q]);
                            mu &= mu - 1;
                        }
                    }
                    // Refresh threshold once per hit-step (can only tighten).
                    thr[q] = fminf(thr[q], __shfl_sync(FULL, kd[q], KNN - 1));
                }
            }
        }
    }

    // ---- Edge lengths + L1: lanes 0..15 hold one neighbor per query ----
    float partial = 0.0f;
    if (lane < KNN) {
#pragma unroll
        for (int q = 0; q < QPW; ++q) {
            const int nb = ki[q];
            float rx = pr[nb * 3 + 0] - qx[q];
            float ry = pr[nb * 3 + 1] - qy[q];
            float rz = pr[nb * 3 + 2] - qz[q];
            float dref = sqrtf(rx * rx + ry * ry + rz * rz);
            float pqx = pp[(q0 + q) * 3 + 0];
            float pqy = pp[(q0 + q) * 3 + 1];
            float pqz = pp[(q0 + q) * 3 + 2];
            float px = pp[nb * 3 + 0] - pqx;
            float py = pp[nb * 3 + 1] - pqy;
            float pz = pp[nb * 3 + 2] - pqz;
            float dprd = sqrtf(px * px + py * py + pz * pz);
            partial += fabsf(dref - dprd);
        }
    }

    // Deterministic warp + block reduction
#pragma unroll
    for (int o = 16; o > 0; o >>= 1)
        partial += __shfl_xor_sync(FULL, partial, o);
    if (lane == 0) wsum[wid] = partial;
    __syncthreads();

    if (wid == 0) {
        float s = (lane < WPB) ? wsum[lane] : 0.0f;
#pragma unroll
        for (int o = 16; o > 0; o >>= 1)
            s += __shfl_xor_sync(FULL, s, o);
        if (lane == 0) g_partials[blockIdx.x] = s;
    }
}

__global__ void finalize_kernel(float* __restrict__ out)
{
    __shared__ double sred[256];
    int t = threadIdx.x;
    double s = 0.0;
    for (int i = t; i < NBLK; i += 256) s += (double)g_partials[i];
    sred[t] = s;
    __syncthreads();
#pragma unroll
    for (int st = 128; st > 0; st >>= 1) {
        if (t < st) sred[t] += sred[t + st];
        __syncthreads();
    }
    if (t == 0) out[0] = (float)(sred[0] / TOTAL_EDGES);
}

extern "C" void kernel_launch(void* const* d_in, const int* in_sizes, int n_in,
                              void* d_out, int out_size)
{
    (void)in_sizes; (void)n_in; (void)out_size;
    const float* points_ref = (const float*)d_in[0];
    const float* points     = (const float*)d_in[1];
    knn_loss_kernel<<<NBLK, BLOCK>>>(points_ref, points);
    finalize_kernel<<<1, 256>>>((float*)d_out);
}